// round 1
// baseline (speedup 1.0000x reference)
#include <cuda_runtime.h>

#define B_ 4
#define C_ 32
#define H_ 1024
#define W_ 64
#define BW_ (B_ * W_)                  // 256 independent attention problems
#define SCALE 0.08838834764831845f     // 1/sqrt(H/NUM_HEAD) = 1/sqrt(128)

// Scratch (allocations are forbidden; __device__ globals are the sanctioned path)
__device__ float g_Q[BW_ * H_ * C_];   // 32 MB, layout [bw][h][c], pre-scaled by SCALE
__device__ float g_K[BW_ * H_ * C_];
__device__ float g_V[BW_ * H_ * C_];
__device__ float g_O[BW_ * H_ * C_];

// ---------------------------------------------------------------------------
// Kernel 1: fused QKV projection.  x:[B,C,H,W] -> Q/K/V:[bw][h][c]
// grid (256 htiles, 4 b), block (64 w, 4 h)
// ---------------------------------------------------------------------------
__global__ void __launch_bounds__(256) proj_kernel(
    const float* __restrict__ x,
    const float* __restrict__ wq, const float* __restrict__ bq,
    const float* __restrict__ wk, const float* __restrict__ bk,
    const float* __restrict__ wv, const float* __restrict__ bv)
{
    __shared__ float sw[3][32][32];
    __shared__ float sb[3][32];
    __shared__ float stage[64][132];   // [w][h*32+o], padded pitch

    const int tx = threadIdx.x;            // w: 0..63
    const int ty = threadIdx.y;            // h sub: 0..3
    const int t  = ty * 64 + tx;           // 0..255
    const int b  = blockIdx.y;
    const int h0 = blockIdx.x * 4;
    const int h  = h0 + ty;

    for (int i = t; i < 1024; i += 256) {
        const int o = i >> 5, c = i & 31;
        sw[0][o][c] = wq[i] * SCALE;       // fold softmax scale into Q
        sw[1][o][c] = wk[i];
        sw[2][o][c] = wv[i];
    }
    if (t < 32) {
        sb[0][t] = bq[t] * SCALE;
        sb[1][t] = bk[t];
        sb[2][t] = bv[t];
    }
    __syncthreads();

    // x[b][c][h][w] — coalesced across tx (w)
    float xv[32];
    const float* xp = x + ((long)b * 32 * H_ + h) * 64 + tx;
    #pragma unroll
    for (int c = 0; c < 32; c++) xv[c] = xp[(long)c * H_ * 64];

    #pragma unroll
    for (int p = 0; p < 3; p++) {
        float* dst = (p == 0) ? g_Q : (p == 1) ? g_K : g_V;
        #pragma unroll
        for (int o = 0; o < 32; o++) {
            float acc = sb[p][o];
            #pragma unroll
            for (int c = 0; c < 32; c++) acc += sw[p][o][c] * xv[c];
            stage[tx][ty * 32 + o] = acc;
        }
        __syncthreads();
        // write out: for each w, 128 contiguous floats at (b*64+w)*H*32 + h0*32
        float* dbase = dst + (long)(b * 64) * H_ * 32 + h0 * 32;
        for (int k4 = t; k4 < 2048; k4 += 256) {
            const int w = k4 >> 5, r4 = k4 & 31;
            *(float4*)(dbase + (long)w * (H_ * 32) + r4 * 4) =
                *(const float4*)&stage[w][r4 * 4];
        }
        __syncthreads();
    }
}

// ---------------------------------------------------------------------------
// Kernel 2: attention.  grid (bw=256, qtile=8), block 256.
// Per CTA: Q tile 128x32, loop 8 KV tiles of 128. exp without max-subtraction
// (scores ~N(0,0.5); max over all samples ~3.2 — safe in fp32).
// ---------------------------------------------------------------------------
struct AttSmem {
    float Qs[128][36];     // [r][c], pitch 36 -> conflict-free float4 along c
    float Ks[128][36];     // [g][c]
    float Vs[128][36];     // [g][c]
    float Es[128][132];    // exp(S), [r][g], pitch 132
    float Pp[16][132];     // per-colgroup partial row sums [tx][r]
    float lsum[128];
};

__global__ void __launch_bounds__(256, 1) att_kernel(
    const float* __restrict__ w_lin, const float* __restrict__ b_lin)
{
    extern __shared__ char smraw[];
    AttSmem& s = *(AttSmem*)smraw;

    const int t  = threadIdx.x;
    const int tx = t & 15;        // col group
    const int ty = t >> 4;        // row group
    const int bw = blockIdx.x;
    const int qt = blockIdx.y;

    // load Q tile (coalesced float4 -> padded smem)
    {
        const float4* src = (const float4*)(g_Q + ((long)bw * H_ + qt * 128) * 32);
        for (int i = t; i < 1024; i += 256) {
            const int r = i >> 3, c4 = i & 7;
            *(float4*)&s.Qs[r][c4 * 4] = src[i];
        }
    }

    float oacc[8][2];
    #pragma unroll
    for (int i = 0; i < 8; i++) { oacc[i][0] = 0.f; oacc[i][1] = 0.f; }
    float l_acc = 0.f;

    for (int kt = 0; kt < 8; kt++) {
        __syncthreads();   // prev tile's consumers done (and Q load on iter 0)
        {
            const float4* ks = (const float4*)(g_K + ((long)bw * H_ + kt * 128) * 32);
            const float4* vs = (const float4*)(g_V + ((long)bw * H_ + kt * 128) * 32);
            for (int i = t; i < 1024; i += 256) {
                const int r = i >> 3, c4 = i & 7;
                *(float4*)&s.Ks[r][c4 * 4] = ks[i];
                *(float4*)&s.Vs[r][c4 * 4] = vs[i];
            }
        }
        __syncthreads();

        // ---- S = Q K^T  (8x8 register tile; rows ty+16i, cols tx+16j) ----
        float acc[8][8];
        #pragma unroll
        for (int i = 0; i < 8; i++)
            #pragma unroll
            for (int j = 0; j < 8; j++) acc[i][j] = 0.f;

        #pragma unroll 1
        for (int c4 = 0; c4 < 8; c4++) {
            float4 qv[8], kv[8];
            #pragma unroll
            for (int i = 0; i < 8; i++) qv[i] = *(const float4*)&s.Qs[ty + 16 * i][c4 * 4];
            #pragma unroll
            for (int j = 0; j < 8; j++) kv[j] = *(const float4*)&s.Ks[tx + 16 * j][c4 * 4];
            #pragma unroll
            for (int i = 0; i < 8; i++)
                #pragma unroll
                for (int j = 0; j < 8; j++) {
                    acc[i][j] += qv[i].x * kv[j].x;
                    acc[i][j] += qv[i].y * kv[j].y;
                    acc[i][j] += qv[i].z * kv[j].z;
                    acc[i][j] += qv[i].w * kv[j].w;
                }
        }

        // ---- E = exp(S), stage to smem, partial row sums ----
        #pragma unroll
        for (int i = 0; i < 8; i++) {
            float rs = 0.f;
            #pragma unroll
            for (int j = 0; j < 8; j++) {
                const float e = __expf(acc[i][j]);
                s.Es[ty + 16 * i][tx + 16 * j] = e;
                rs += e;
            }
            s.Pp[tx][ty + 16 * i] = rs;
        }
        __syncthreads();

        if (t < 128) {  // row owner reduces 16 partials
            float sum = 0.f;
            #pragma unroll
            for (int k = 0; k < 16; k++) sum += s.Pp[k][t];
            l_acc += sum;
        }

        // ---- O += E V  (8 rows ty+16i, cols tx and tx+16) ----
        #pragma unroll 1
        for (int g4 = 0; g4 < 32; g4++) {
            float4 ev[8];
            #pragma unroll
            for (int i = 0; i < 8; i++) ev[i] = *(const float4*)&s.Es[ty + 16 * i][g4 * 4];
            #pragma unroll
            for (int gg = 0; gg < 4; gg++) {
                const int g = g4 * 4 + gg;
                const float v0 = s.Vs[g][tx];
                const float v1 = s.Vs[g][tx + 16];
                #pragma unroll
                for (int i = 0; i < 8; i++) {
                    const float e = (gg == 0) ? ev[i].x : (gg == 1) ? ev[i].y
                                  : (gg == 2) ? ev[i].z : ev[i].w;
                    oacc[i][0] += e * v0;
                    oacc[i][1] += e * v1;
                }
            }
        }
    }

    if (t < 128) s.lsum[t] = l_acc;
    __syncthreads();

    float ws = 0.f;
    #pragma unroll
    for (int k = 0; k < 8; k++) ws += w_lin[k];
    const float b0 = b_lin[0];

    float* obase = g_O + ((long)bw * H_ + qt * 128) * 32;
    #pragma unroll
    for (int i = 0; i < 8; i++) {
        const int r = ty + 16 * i;
        const float f = ws / s.lsum[r];
        obase[r * 32 + tx]      = oacc[i][0] * f + b0;
        obase[r * 32 + tx + 16] = oacc[i][1] * f + b0;
    }
}

// ---------------------------------------------------------------------------
// Kernel 3: epilogue transpose  g_O [bw][h][c]  ->  out [b][c][h][w]
// grid (2 w-halves, 1024 h, 4 b), block (32, 8)
// ---------------------------------------------------------------------------
__global__ void __launch_bounds__(256) transpose_kernel(float* __restrict__ out)
{
    __shared__ float tile[32][33];
    const int b  = blockIdx.z;
    const int h  = blockIdx.y;
    const int w0 = blockIdx.x * 32;

    for (int wi = threadIdx.y; wi < 32; wi += 8)
        tile[wi][threadIdx.x] =
            g_O[(((long)(b * 64 + w0 + wi)) * H_ + h) * 32 + threadIdx.x];
    __syncthreads();
    for (int c = threadIdx.y; c < 32; c += 8)
        out[(((long)(b * 32 + c)) * H_ + h) * 64 + w0 + threadIdx.x] =
            tile[threadIdx.x][c];
}

// ---------------------------------------------------------------------------
extern "C" void kernel_launch(void* const* d_in, const int* in_sizes, int n_in,
                              void* d_out, int out_size)
{
    const float* x  = (const float*)d_in[0];
    const float* wq = (const float*)d_in[1];
    const float* bq = (const float*)d_in[2];
    const float* wk = (const float*)d_in[3];
    const float* bk = (const float*)d_in[4];
    const float* wv = (const float*)d_in[5];
    const float* bv = (const float*)d_in[6];
    const float* wl = (const float*)d_in[7];
    const float* bl = (const float*)d_in[8];
    float* out = (float*)d_out;

    cudaFuncSetAttribute(att_kernel, cudaFuncAttributeMaxDynamicSharedMemorySize,
                         (int)sizeof(AttSmem));

    proj_kernel<<<dim3(256, 4), dim3(64, 4)>>>(x, wq, bq, wk, bk, wv, bv);
    att_kernel<<<dim3(256, 8), 256, sizeof(AttSmem)>>>(wl, bl);
    transpose_kernel<<<dim3(2, 1024, 4), dim3(32, 8)>>>(out);
}

// round 4
// speedup vs baseline: 2.9328x; 2.9328x over previous
#include <cuda_runtime.h>
#include <cuda_bf16.h>
#include <cstdint>

#define B_ 4
#define C_ 32
#define H_ 1024
#define W_ 64
#define BW_ 256
#define SCALE 0.08838834764831845f     // 1/sqrt(H/NUM_HEAD) = 1/sqrt(128)

// Scratch (__device__ globals; allocations forbidden). bf16 hi/lo pairs.
__device__ __nv_bfloat16 g_Qh[BW_ * H_ * C_];   // [bw][h][c]
__device__ __nv_bfloat16 g_Ql[BW_ * H_ * C_];
__device__ __nv_bfloat16 g_Kh[BW_ * H_ * C_];
__device__ __nv_bfloat16 g_Kl[BW_ * H_ * C_];
__device__ __nv_bfloat16 g_Vh[BW_ * H_ * C_];
__device__ __nv_bfloat16 g_Vl[BW_ * H_ * C_];
__device__ float g_O[BW_ * H_ * C_];            // [bw][h][c] fp32

// ---------------------------------------------------------------------------
// helpers
// ---------------------------------------------------------------------------
__device__ __forceinline__ uint32_t smem_u32(const void* p) {
    uint32_t a;
    asm("{ .reg .u64 t; cvta.to.shared.u64 t, %1; cvt.u32.u64 %0, t; }" : "=r"(a) : "l"(p));
    return a;
}
__device__ __forceinline__ uint32_t lds32(uint32_t a) {
    uint32_t v;
    asm volatile("ld.shared.b32 %0, [%1];" : "=r"(v) : "r"(a));
    return v;
}
// pack two fp32 -> bf16x2, e0 in low half, e1 in high half
__device__ __forceinline__ uint32_t pk(float e0, float e1) {
    uint32_t r;
    asm("cvt.rn.bf16x2.f32 %0, %1, %2;" : "=r"(r) : "f"(e1), "f"(e0));
    return r;
}
__device__ __forceinline__ float bhi(float x) {
    return __bfloat162float(__float2bfloat16_rn(x));
}

#define MMA16816(d, a0, a1, a2, a3, b0, b1)                                    \
    asm volatile("mma.sync.aligned.m16n8k16.row.col.f32.bf16.bf16.f32 "        \
        "{%0,%1,%2,%3}, {%4,%5,%6,%7}, {%8,%9}, {%0,%1,%2,%3};"                \
        : "+f"((d)[0]), "+f"((d)[1]), "+f"((d)[2]), "+f"((d)[3])               \
        : "r"(a0), "r"(a1), "r"(a2), "r"(a3), "r"(b0), "r"(b1))

#define LDMX2T(r0, r1, addr)                                                   \
    asm volatile("ldmatrix.sync.aligned.m8n8.x2.trans.shared.b16 {%0,%1}, [%2];" \
        : "=r"(r0), "=r"(r1) : "r"(addr))

// ---------------------------------------------------------------------------
// Kernel 1: fused QKV projection -> bf16 hi/lo, [bw][h][32]
// grid (256 htiles, 4 b), block (64 w, 4 h)
// ---------------------------------------------------------------------------
__global__ void __launch_bounds__(256) proj_kernel(
    const float* __restrict__ x,
    const float* __restrict__ wq, const float* __restrict__ bq,
    const float* __restrict__ wk, const float* __restrict__ bk,
    const float* __restrict__ wv, const float* __restrict__ bv)
{
    __shared__ float sw[3][32][32];
    __shared__ float sb[3][32];
    __shared__ uint32_t sh[64][67];   // hi bf16x2 stage  [w][ty*16 + chpair]
    __shared__ uint32_t sl[64][67];   // lo bf16x2 stage

    const int tx = threadIdx.x, ty = threadIdx.y;
    const int t = ty * 64 + tx;
    const int b = blockIdx.y;
    const int h0 = blockIdx.x * 4;
    const int h = h0 + ty;

    for (int i = t; i < 1024; i += 256) {
        const int o = i >> 5, c = i & 31;
        sw[0][o][c] = wq[i] * SCALE;
        sw[1][o][c] = wk[i];
        sw[2][o][c] = wv[i];
    }
    if (t < 32) { sb[0][t] = bq[t] * SCALE; sb[1][t] = bk[t]; sb[2][t] = bv[t]; }
    __syncthreads();

    float xv[32];
    const float* xp = x + ((long)b * 32 * H_ + h) * 64 + tx;
    #pragma unroll
    for (int c = 0; c < 32; c++) xv[c] = xp[(long)c * H_ * 64];

    #pragma unroll
    for (int p = 0; p < 3; p++) {
        __nv_bfloat16* dh = (p == 0) ? g_Qh : (p == 1) ? g_Kh : g_Vh;
        __nv_bfloat16* dl = (p == 0) ? g_Ql : (p == 1) ? g_Kl : g_Vl;
        #pragma unroll
        for (int o = 0; o < 32; o += 2) {
            float a0 = sb[p][o], a1 = sb[p][o + 1];
            #pragma unroll
            for (int c = 0; c < 32; c++) {
                a0 += sw[p][o][c] * xv[c];
                a1 += sw[p][o + 1][c] * xv[c];
            }
            float h0f = bhi(a0), h1f = bhi(a1);
            sh[tx][ty * 16 + (o >> 1)] = pk(h0f, h1f);
            sl[tx][ty * 16 + (o >> 1)] = pk(a0 - h0f, a1 - h1f);
        }
        __syncthreads();
        // writeout: per w, 64 uints (4 rows x 16 chpairs) contiguous in gmem
        uint32_t* gh = (uint32_t*)dh;
        uint32_t* gl = (uint32_t*)dl;
        const long cbase = (long)(b * 64) * 16384 + h0 * 16;
        for (int i = t; i < 4096; i += 256) {
            const int w = i >> 6, j = i & 63;
            gh[cbase + (long)w * 16384 + j] = sh[w][j];
            gl[cbase + (long)w * 16384 + j] = sl[w][j];
        }
        __syncthreads();
    }
}

// ---------------------------------------------------------------------------
// Kernel 2: attention via mma.sync m16n8k16 bf16 (3-pass hi/lo).
// grid (bw=256, qt=8), block 256 (8 warps, warp owns 16 q rows).
// smem rows are 80B pitch (64B data + 16B pad) -> conflict-free frag loads.
// ---------------------------------------------------------------------------
#define SQH 0
#define SQL 10240
#define SKH 20480
#define SKL 30720
#define SVH 40960
#define SVL 51200
#define ATT_SMEM 61440

__global__ void __launch_bounds__(256, 2) att3_kernel(
    const float* __restrict__ w_lin, const float* __restrict__ b_lin)
{
    extern __shared__ char sm[];
    const uint32_t sbase = smem_u32(sm);

    const int t = threadIdx.x;
    const int lane = t & 31, warp = t >> 5;
    const int bw = blockIdx.x, qt = blockIdx.y;

    const int qrow = lane >> 2;         // 0..7
    const int lc4 = (lane & 3) * 4;     // byte offset of ch/token pair
    const int wr = warp * 16;

    // ---- load Q tile (hi/lo) into smem ----
    {
        const uint4* qh = (const uint4*)(g_Qh + ((size_t)bw * H_ + (size_t)qt * 128) * 32);
        const uint4* ql = (const uint4*)(g_Ql + ((size_t)bw * H_ + (size_t)qt * 128) * 32);
        for (int i = t; i < 512; i += 256) {
            const int row = i >> 2, q = i & 3;
            *(uint4*)(sm + SQH + row * 80 + q * 16) = qh[i];
            *(uint4*)(sm + SQL + row * 80 + q * 16) = ql[i];
        }
    }

    float sacc[16][4];
    float oacc[4][4];
    #pragma unroll
    for (int n = 0; n < 4; n++)
        #pragma unroll
        for (int e = 0; e < 4; e++) oacc[n][e] = 0.f;
    float rs0 = 0.f, rs1 = 0.f;

    for (int kt = 0; kt < 8; kt++) {
        __syncthreads();   // K/V smem consumers of prev tile done (Q ready on kt=0)
        {
            const size_t tbase = ((size_t)bw * H_ + (size_t)kt * 128) * 32;
            const uint4* kh = (const uint4*)(g_Kh + tbase);
            const uint4* kl = (const uint4*)(g_Kl + tbase);
            const uint4* vh = (const uint4*)(g_Vh + tbase);
            const uint4* vl = (const uint4*)(g_Vl + tbase);
            for (int i = t; i < 512; i += 256) {
                const int row = i >> 2, q = i & 3;
                const int o = row * 80 + q * 16;
                *(uint4*)(sm + SKH + o) = kh[i];
                *(uint4*)(sm + SKL + o) = kl[i];
                *(uint4*)(sm + SVH + o) = vh[i];
                *(uint4*)(sm + SVL + o) = vl[i];
            }
        }
        __syncthreads();

        // ---- S = Q K^T (3-pass) ----
        #pragma unroll
        for (int nt = 0; nt < 16; nt++) {
            sacc[nt][0] = 0.f; sacc[nt][1] = 0.f; sacc[nt][2] = 0.f; sacc[nt][3] = 0.f;
        }
        #pragma unroll
        for (int ks = 0; ks < 2; ks++) {
            const uint32_t aq = sbase + SQH + (wr + qrow) * 80 + lc4 + ks * 32;
            const uint32_t qh0 = lds32(aq),        qh1 = lds32(aq + 640);
            const uint32_t qh2 = lds32(aq + 16),   qh3 = lds32(aq + 656);
            const uint32_t ql0 = lds32(aq + 10240), ql1 = lds32(aq + 10880);
            const uint32_t ql2 = lds32(aq + 10256), ql3 = lds32(aq + 10896);
            #pragma unroll
            for (int nt = 0; nt < 16; nt++) {
                const uint32_t bk = sbase + SKH + (nt * 8 + qrow) * 80 + lc4 + ks * 32;
                const uint32_t kh0 = lds32(bk),         kh1 = lds32(bk + 16);
                const uint32_t kl0 = lds32(bk + 10240), kl1 = lds32(bk + 10256);
                MMA16816(sacc[nt], qh0, qh1, qh2, qh3, kh0, kh1);
                MMA16816(sacc[nt], qh0, qh1, qh2, qh3, kl0, kl1);
                MMA16816(sacc[nt], ql0, ql1, ql2, ql3, kh0, kh1);
            }
        }

        // ---- P = exp(S) in registers + row sums ----
        #pragma unroll
        for (int nt = 0; nt < 16; nt++) {
            const float e0 = __expf(sacc[nt][0]);
            const float e1 = __expf(sacc[nt][1]);
            const float e2 = __expf(sacc[nt][2]);
            const float e3 = __expf(sacc[nt][3]);
            rs0 += e0 + e1;
            rs1 += e2 + e3;
            sacc[nt][0] = e0; sacc[nt][1] = e1; sacc[nt][2] = e2; sacc[nt][3] = e3;
        }

        // ---- O += P V (3-pass); A-frags straight from S accumulators ----
        #pragma unroll
        for (int ks = 0; ks < 8; ks++) {
            const float* p0 = sacc[2 * ks];
            const float* p1 = sacc[2 * ks + 1];
            const float h00 = bhi(p0[0]), h01 = bhi(p0[1]), h02 = bhi(p0[2]), h03 = bhi(p0[3]);
            const float h10 = bhi(p1[0]), h11 = bhi(p1[1]), h12 = bhi(p1[2]), h13 = bhi(p1[3]);
            const uint32_t ah0 = pk(h00, h01), ah1 = pk(h02, h03);
            const uint32_t ah2 = pk(h10, h11), ah3 = pk(h12, h13);
            const uint32_t al0 = pk(p0[0] - h00, p0[1] - h01), al1 = pk(p0[2] - h02, p0[3] - h03);
            const uint32_t al2 = pk(p1[0] - h10, p1[1] - h11), al3 = pk(p1[2] - h12, p1[3] - h13);
            const uint32_t va = sbase + SVH + (ks * 16 + (lane & 15)) * 80;
            #pragma unroll
            for (int nt = 0; nt < 4; nt++) {
                uint32_t vh0, vh1, vl0, vl1;
                LDMX2T(vh0, vh1, va + nt * 16);
                LDMX2T(vl0, vl1, va + nt * 16 + 10240);
                MMA16816(oacc[nt], ah0, ah1, ah2, ah3, vh0, vh1);
                MMA16816(oacc[nt], ah0, ah1, ah2, ah3, vl0, vl1);
                MMA16816(oacc[nt], al0, al1, al2, al3, vh0, vh1);
            }
        }
    }

    // ---- finalize: row sums across quad, scale+bias, store ----
    rs0 += __shfl_xor_sync(0xffffffffu, rs0, 1);
    rs0 += __shfl_xor_sync(0xffffffffu, rs0, 2);
    rs1 += __shfl_xor_sync(0xffffffffu, rs1, 1);
    rs1 += __shfl_xor_sync(0xffffffffu, rs1, 2);

    float ws = 0.f;
    #pragma unroll
    for (int k = 0; k < 8; k++) ws += w_lin[k];
    const float bb = b_lin[0];
    const float f0 = ws / rs0, f1 = ws / rs1;

    const int row = qt * 128 + wr + qrow;
    float* ob = g_O + ((size_t)bw * H_ + row) * 32 + (lane & 3) * 2;
    #pragma unroll
    for (int nt = 0; nt < 4; nt++) {
        float2 v0 = make_float2(oacc[nt][0] * f0 + bb, oacc[nt][1] * f0 + bb);
        float2 v1 = make_float2(oacc[nt][2] * f1 + bb, oacc[nt][3] * f1 + bb);
        *(float2*)(ob + nt * 8) = v0;
        *(float2*)(ob + 8 * 32 + nt * 8) = v1;
    }
}

// ---------------------------------------------------------------------------
// Kernel 3: epilogue transpose  g_O [bw][h][c] -> out [b][c][h][w]
// ---------------------------------------------------------------------------
__global__ void __launch_bounds__(256) transpose_kernel(float* __restrict__ out)
{
    __shared__ float tile[32][33];
    const int b = blockIdx.z, h = blockIdx.y, w0 = blockIdx.x * 32;

    for (int wi = threadIdx.y; wi < 32; wi += 8)
        tile[wi][threadIdx.x] = g_O[(((long)(b * 64 + w0 + wi)) * H_ + h) * 32 + threadIdx.x];
    __syncthreads();
    for (int c = threadIdx.y; c < 32; c += 8)
        out[(((long)(b * 32 + c)) * H_ + h) * 64 + w0 + threadIdx.x] = tile[threadIdx.x][c];
}

// ---------------------------------------------------------------------------
extern "C" void kernel_launch(void* const* d_in, const int* in_sizes, int n_in,
                              void* d_out, int out_size)
{
    const float* x  = (const float*)d_in[0];
    const float* wq = (const float*)d_in[1];
    const float* bq = (const float*)d_in[2];
    const float* wk = (const float*)d_in[3];
    const float* bk = (const float*)d_in[4];
    const float* wv = (const float*)d_in[5];
    const float* bv = (const float*)d_in[6];
    const float* wl = (const float*)d_in[7];
    const float* bl = (const float*)d_in[8];
    float* out = (float*)d_out;

    cudaFuncSetAttribute(att3_kernel, cudaFuncAttributeMaxDynamicSharedMemorySize, ATT_SMEM);

    proj_kernel<<<dim3(256, 4), dim3(64, 4)>>>(x, wq, bq, wk, bk, wv, bv);
    att3_kernel<<<dim3(256, 8), 256, ATT_SMEM>>>(wl, bl);
    transpose_kernel<<<dim3(2, 1024, 4), dim3(32, 8)>>>(out);
}

// round 5
// speedup vs baseline: 4.0016x; 1.3644x over previous
#include <cuda_runtime.h>
#include <cuda_fp16.h>
#include <cstdint>

#define B_ 4
#define C_ 32
#define H_ 1024
#define W_ 64
#define BW_ 256
#define SCALE 0.08838834764831845f     // 1/sqrt(H/NUM_HEAD) = 1/sqrt(128)

// Scratch (__device__ globals; allocations forbidden).
// Q kept as fp16 hi+lo (exact-ish); K,V single fp16 (their rounding is the
// only GEMM error: ~2^-13 random-walk, ~1e-4 << 1e-3 tolerance).
__device__ __half g_Qh[BW_ * H_ * C_];   // [bw][h][c]
__device__ __half g_Ql[BW_ * H_ * C_];
__device__ __half g_K [BW_ * H_ * C_];
__device__ __half g_V [BW_ * H_ * C_];
__device__ float  g_O [BW_ * H_ * C_];   // [bw][h][c] fp32

// ---------------------------------------------------------------------------
// helpers
// ---------------------------------------------------------------------------
__device__ __forceinline__ uint32_t smem_u32(const void* p) {
    uint32_t a;
    asm("{ .reg .u64 t; cvta.to.shared.u64 t, %1; cvt.u32.u64 %0, t; }" : "=r"(a) : "l"(p));
    return a;
}
__device__ __forceinline__ uint32_t lds32(uint32_t a) {
    uint32_t v;
    asm volatile("ld.shared.b32 %0, [%1];" : "=r"(v) : "r"(a));
    return v;
}
// pack two fp32 -> f16x2, e0 low half, e1 high half
__device__ __forceinline__ uint32_t pk(float e0, float e1) {
    uint32_t r;
    asm("cvt.rn.f16x2.f32 %0, %1, %2;" : "=r"(r) : "f"(e1), "f"(e0));
    return r;
}
__device__ __forceinline__ float hrd(float x) {
    return __half2float(__float2half_rn(x));
}

#define MMA16816(d, a0, a1, a2, a3, b0, b1)                                    \
    asm volatile("mma.sync.aligned.m16n8k16.row.col.f32.f16.f16.f32 "          \
        "{%0,%1,%2,%3}, {%4,%5,%6,%7}, {%8,%9}, {%0,%1,%2,%3};"                \
        : "+f"((d)[0]), "+f"((d)[1]), "+f"((d)[2]), "+f"((d)[3])               \
        : "r"(a0), "r"(a1), "r"(a2), "r"(a3), "r"(b0), "r"(b1))

#define LDMX2T(r0, r1, addr)                                                   \
    asm volatile("ldmatrix.sync.aligned.m8n8.x2.trans.shared.b16 {%0,%1}, [%2];" \
        : "=r"(r0), "=r"(r1) : "r"(addr))

// ---------------------------------------------------------------------------
// Kernel 1: fused QKV projection -> fp16 (Q hi/lo, K, V), layout [bw][h][32]
// grid (256 htiles, 4 b), block (64 w, 4 h)
// ---------------------------------------------------------------------------
__global__ void __launch_bounds__(256) proj_kernel(
    const float* __restrict__ x,
    const float* __restrict__ wq, const float* __restrict__ bq,
    const float* __restrict__ wk, const float* __restrict__ bk,
    const float* __restrict__ wv, const float* __restrict__ bv)
{
    __shared__ float sw[3][32][32];
    __shared__ float sb[3][32];
    __shared__ uint32_t sh[64][67];   // hi f16x2 stage  [w][ty*16 + chpair]
    __shared__ uint32_t sl[64][67];   // lo f16x2 stage (Q only)

    const int tx = threadIdx.x, ty = threadIdx.y;
    const int t = ty * 64 + tx;
    const int b = blockIdx.y;
    const int h0 = blockIdx.x * 4;
    const int h = h0 + ty;

    for (int i = t; i < 1024; i += 256) {
        const int o = i >> 5, c = i & 31;
        sw[0][o][c] = wq[i] * SCALE;
        sw[1][o][c] = wk[i];
        sw[2][o][c] = wv[i];
    }
    if (t < 32) { sb[0][t] = bq[t] * SCALE; sb[1][t] = bk[t]; sb[2][t] = bv[t]; }
    __syncthreads();

    float xv[32];
    const float* xp = x + ((long)b * 32 * H_ + h) * 64 + tx;
    #pragma unroll
    for (int c = 0; c < 32; c++) xv[c] = xp[(long)c * H_ * 64];

    #pragma unroll
    for (int p = 0; p < 3; p++) {
        __half* dh = (p == 0) ? g_Qh : (p == 1) ? g_K : g_V;
        #pragma unroll
        for (int o = 0; o < 32; o += 2) {
            float a0 = sb[p][o], a1 = sb[p][o + 1];
            #pragma unroll
            for (int c = 0; c < 32; c++) {
                a0 += sw[p][o][c] * xv[c];
                a1 += sw[p][o + 1][c] * xv[c];
            }
            if (p == 0) {
                float h0f = hrd(a0), h1f = hrd(a1);
                sh[tx][ty * 16 + (o >> 1)] = pk(h0f, h1f);
                sl[tx][ty * 16 + (o >> 1)] = pk(a0 - h0f, a1 - h1f);
            } else {
                sh[tx][ty * 16 + (o >> 1)] = pk(a0, a1);
            }
        }
        __syncthreads();
        // writeout: per w, 64 uints (4 rows x 16 chpairs) contiguous in gmem
        uint32_t* gh = (uint32_t*)dh;
        uint32_t* gl = (uint32_t*)g_Ql;
        const long cbase = (long)(b * 64) * 16384 + h0 * 16;
        for (int i = t; i < 4096; i += 256) {
            const int w = i >> 6, j = i & 63;
            gh[cbase + (long)w * 16384 + j] = sh[w][j];
            if (p == 0) gl[cbase + (long)w * 16384 + j] = sl[w][j];
        }
        __syncthreads();
    }
}

// ---------------------------------------------------------------------------
// Kernel 2: attention via mma.sync m16n8k16 fp16 (2-pass hi/lo on A side).
// grid (bw=256, qt=8), block 256 (8 warps, warp owns 16 q rows).
// smem rows are 80B pitch (64B data + 16B pad) -> conflict-free frag loads.
// ---------------------------------------------------------------------------
#define SQH 0
#define SQL 10240
#define SK  20480
#define SV  30720
#define ATT_SMEM 40960

__global__ void __launch_bounds__(256, 2) att3_kernel(
    const float* __restrict__ w_lin, const float* __restrict__ b_lin)
{
    extern __shared__ char sm[];
    const uint32_t sbase = smem_u32(sm);

    const int t = threadIdx.x;
    const int lane = t & 31, warp = t >> 5;
    const int bw = blockIdx.x, qt = blockIdx.y;

    const int qrow = lane >> 2;         // 0..7
    const int lc4 = (lane & 3) * 4;     // byte offset of ch/token pair
    const int wr = warp * 16;

    // ---- load Q tile (hi/lo) into smem ----
    {
        const uint4* qh = (const uint4*)(g_Qh + ((size_t)bw * H_ + (size_t)qt * 128) * 32);
        const uint4* ql = (const uint4*)(g_Ql + ((size_t)bw * H_ + (size_t)qt * 128) * 32);
        for (int i = t; i < 512; i += 256) {
            const int row = i >> 2, q = i & 3;
            *(uint4*)(sm + SQH + row * 80 + q * 16) = qh[i];
            *(uint4*)(sm + SQL + row * 80 + q * 16) = ql[i];
        }
    }

    float sacc[16][4];
    float oacc[4][4];
    #pragma unroll
    for (int n = 0; n < 4; n++)
        #pragma unroll
        for (int e = 0; e < 4; e++) oacc[n][e] = 0.f;
    float rs0 = 0.f, rs1 = 0.f;

    for (int kt = 0; kt < 8; kt++) {
        __syncthreads();   // K/V smem consumers of prev tile done (Q ready on kt=0)
        {
            const size_t tbase = ((size_t)bw * H_ + (size_t)kt * 128) * 32;
            const uint4* kh = (const uint4*)(g_K + tbase);
            const uint4* vh = (const uint4*)(g_V + tbase);
            for (int i = t; i < 512; i += 256) {
                const int row = i >> 2, q = i & 3;
                const int o = row * 80 + q * 16;
                *(uint4*)(sm + SK + o) = kh[i];
                *(uint4*)(sm + SV + o) = vh[i];
            }
        }
        __syncthreads();

        // ---- S = Q K^T (2-pass: (Qh+Ql)·K) ----
        #pragma unroll
        for (int nt = 0; nt < 16; nt++) {
            sacc[nt][0] = 0.f; sacc[nt][1] = 0.f; sacc[nt][2] = 0.f; sacc[nt][3] = 0.f;
        }
        #pragma unroll
        for (int ks = 0; ks < 2; ks++) {
            const uint32_t aq = sbase + SQH + (wr + qrow) * 80 + lc4 + ks * 32;
            const uint32_t qh0 = lds32(aq),         qh1 = lds32(aq + 640);
            const uint32_t qh2 = lds32(aq + 16),    qh3 = lds32(aq + 656);
            const uint32_t ql0 = lds32(aq + 10240), ql1 = lds32(aq + 10880);
            const uint32_t ql2 = lds32(aq + 10256), ql3 = lds32(aq + 10896);
            #pragma unroll
            for (int nt = 0; nt < 16; nt++) {
                const uint32_t bk = sbase + SK + (nt * 8 + qrow) * 80 + lc4 + ks * 32;
                const uint32_t kh0 = lds32(bk), kh1 = lds32(bk + 16);
                MMA16816(sacc[nt], qh0, qh1, qh2, qh3, kh0, kh1);
                MMA16816(sacc[nt], ql0, ql1, ql2, ql3, kh0, kh1);
            }
        }

        // ---- P = exp(S) in registers + row sums ----
        #pragma unroll
        for (int nt = 0; nt < 16; nt++) {
            const float e0 = __expf(sacc[nt][0]);
            const float e1 = __expf(sacc[nt][1]);
            const float e2 = __expf(sacc[nt][2]);
            const float e3 = __expf(sacc[nt][3]);
            rs0 += e0 + e1;
            rs1 += e2 + e3;
            sacc[nt][0] = e0; sacc[nt][1] = e1; sacc[nt][2] = e2; sacc[nt][3] = e3;
        }

        // ---- O += P V (2-pass: (Ph+Pl)·V); A-frags from S accumulators ----
        #pragma unroll
        for (int ks = 0; ks < 8; ks++) {
            const float* p0 = sacc[2 * ks];
            const float* p1 = sacc[2 * ks + 1];
            const float h00 = hrd(p0[0]), h01 = hrd(p0[1]), h02 = hrd(p0[2]), h03 = hrd(p0[3]);
            const float h10 = hrd(p1[0]), h11 = hrd(p1[1]), h12 = hrd(p1[2]), h13 = hrd(p1[3]);
            const uint32_t ah0 = pk(h00, h01), ah1 = pk(h02, h03);
            const uint32_t ah2 = pk(h10, h11), ah3 = pk(h12, h13);
            const uint32_t al0 = pk(p0[0] - h00, p0[1] - h01), al1 = pk(p0[2] - h02, p0[3] - h03);
            const uint32_t al2 = pk(p1[0] - h10, p1[1] - h11), al3 = pk(p1[2] - h12, p1[3] - h13);
            const uint32_t va = sbase + SV + (ks * 16 + (lane & 15)) * 80;
            #pragma unroll
            for (int nt = 0; nt < 4; nt++) {
                uint32_t vh0, vh1;
                LDMX2T(vh0, vh1, va + nt * 16);
                MMA16816(oacc[nt], ah0, ah1, ah2, ah3, vh0, vh1);
                MMA16816(oacc[nt], al0, al1, al2, al3, vh0, vh1);
            }
        }
    }

    // ---- finalize: row sums across quad, scale+bias, store ----
    rs0 += __shfl_xor_sync(0xffffffffu, rs0, 1);
    rs0 += __shfl_xor_sync(0xffffffffu, rs0, 2);
    rs1 += __shfl_xor_sync(0xffffffffu, rs1, 1);
    rs1 += __shfl_xor_sync(0xffffffffu, rs1, 2);

    float ws = 0.f;
    #pragma unroll
    for (int k = 0; k < 8; k++) ws += w_lin[k];
    const float bb = b_lin[0];
    const float f0 = ws / rs0, f1 = ws / rs1;

    const int row = qt * 128 + wr + qrow;
    float* ob = g_O + ((size_t)bw * H_ + row) * 32 + (lane & 3) * 2;
    #pragma unroll
    for (int nt = 0; nt < 4; nt++) {
        float2 v0 = make_float2(oacc[nt][0] * f0 + bb, oacc[nt][1] * f0 + bb);
        float2 v1 = make_float2(oacc[nt][2] * f1 + bb, oacc[nt][3] * f1 + bb);
        *(float2*)(ob + nt * 8) = v0;
        *(float2*)(ob + 8 * 32 + nt * 8) = v1;
    }
}

// ---------------------------------------------------------------------------
// Kernel 3: epilogue transpose  g_O [bw][h][c] -> out [b][c][h][w]
// ---------------------------------------------------------------------------
__global__ void __launch_bounds__(256) transpose_kernel(float* __restrict__ out)
{
    __shared__ float tile[32][33];
    const int b = blockIdx.z, h = blockIdx.y, w0 = blockIdx.x * 32;

    for (int wi = threadIdx.y; wi < 32; wi += 8)
        tile[wi][threadIdx.x] = g_O[(((long)(b * 64 + w0 + wi)) * H_ + h) * 32 + threadIdx.x];
    __syncthreads();
    for (int c = threadIdx.y; c < 32; c += 8)
        out[(((long)(b * 32 + c)) * H_ + h) * 64 + w0 + threadIdx.x] = tile[threadIdx.x][c];
}

// ---------------------------------------------------------------------------
extern "C" void kernel_launch(void* const* d_in, const int* in_sizes, int n_in,
                              void* d_out, int out_size)
{
    const float* x  = (const float*)d_in[0];
    const float* wq = (const float*)d_in[1];
    const float* bq = (const float*)d_in[2];
    const float* wk = (const float*)d_in[3];
    const float* bk = (const float*)d_in[4];
    const float* wv = (const float*)d_in[5];
    const float* bv = (const float*)d_in[6];
    const float* wl = (const float*)d_in[7];
    const float* bl = (const float*)d_in[8];
    float* out = (float*)d_out;

    cudaFuncSetAttribute(att3_kernel, cudaFuncAttributeMaxDynamicSharedMemorySize, ATT_SMEM);

    proj_kernel<<<dim3(256, 4), dim3(64, 4)>>>(x, wq, bq, wk, bk, wv, bv);
    att3_kernel<<<dim3(256, 8), 256, ATT_SMEM>>>(wl, bl);
    transpose_kernel<<<dim3(2, 1024, 4), dim3(32, 8)>>>(out);
}

// round 6
// speedup vs baseline: 5.7684x; 1.4415x over previous
#include <cuda_runtime.h>
#include <cuda_fp16.h>
#include <cstdint>

#define B_ 4
#define C_ 32
#define H_ 1024
#define W_ 64
#define BW_ 256
#define SCALE 0.08838834764831845f     // 1/sqrt(H/NUM_HEAD) = 1/sqrt(128)

// Scratch (__device__ globals; allocations forbidden). All single fp16:
// total rounding error ~2e-4 << 1e-3 tolerance (calibrated R4/R5).
__device__ __half g_Q[BW_ * H_ * C_];   // [bw][h][c], pre-scaled by SCALE
__device__ __half g_K[BW_ * H_ * C_];
__device__ __half g_V[BW_ * H_ * C_];
__device__ float  g_O[BW_ * H_ * C_];   // [bw][h][c] fp32

// ---------------------------------------------------------------------------
// helpers
// ---------------------------------------------------------------------------
__device__ __forceinline__ uint32_t smem_u32(const void* p) {
    uint32_t a;
    asm("{ .reg .u64 t; cvta.to.shared.u64 t, %1; cvt.u32.u64 %0, t; }" : "=r"(a) : "l"(p));
    return a;
}
__device__ __forceinline__ uint32_t lds32(uint32_t a) {
    uint32_t v;
    asm volatile("ld.shared.b32 %0, [%1];" : "=r"(v) : "r"(a));
    return v;
}
// pack two fp32 -> f16x2, e0 low half, e1 high half
__device__ __forceinline__ uint32_t pk(float e0, float e1) {
    uint32_t r;
    asm("cvt.rn.f16x2.f32 %0, %1, %2;" : "=r"(r) : "f"(e1), "f"(e0));
    return r;
}

#define MMA16816(d, a0, a1, a2, a3, b0, b1)                                    \
    asm volatile("mma.sync.aligned.m16n8k16.row.col.f32.f16.f16.f32 "          \
        "{%0,%1,%2,%3}, {%4,%5,%6,%7}, {%8,%9}, {%0,%1,%2,%3};"                \
        : "+f"((d)[0]), "+f"((d)[1]), "+f"((d)[2]), "+f"((d)[3])               \
        : "r"(a0), "r"(a1), "r"(a2), "r"(a3), "r"(b0), "r"(b1))

#define LDMX2T(r0, r1, addr)                                                   \
    asm volatile("ldmatrix.sync.aligned.m8n8.x2.trans.shared.b16 {%0,%1}, [%2];" \
        : "=r"(r0), "=r"(r1) : "r"(addr))

#define CP16(dst, src)                                                         \
    asm volatile("cp.async.cg.shared.global [%0], [%1], 16;" :: "r"(dst), "l"(src))
#define CP_COMMIT() asm volatile("cp.async.commit_group;")
#define CP_WAIT(n)  asm volatile("cp.async.wait_group %0;" :: "n"(n))

// ---------------------------------------------------------------------------
// Kernel 1: fused QKV projection -> fp16, layout [bw][h][32]
// grid (256 htiles, 4 b), block (64 w, 4 h)
// ---------------------------------------------------------------------------
__global__ void __launch_bounds__(256) proj_kernel(
    const float* __restrict__ x,
    const float* __restrict__ wq, const float* __restrict__ bq,
    const float* __restrict__ wk, const float* __restrict__ bk,
    const float* __restrict__ wv, const float* __restrict__ bv)
{
    __shared__ float sw[3][32][32];
    __shared__ float sb[3][32];
    __shared__ uint32_t sh[64][67];   // f16x2 stage  [w][ty*16 + chpair]

    const int tx = threadIdx.x, ty = threadIdx.y;
    const int t = ty * 64 + tx;
    const int b = blockIdx.y;
    const int h0 = blockIdx.x * 4;
    const int h = h0 + ty;

    for (int i = t; i < 1024; i += 256) {
        const int o = i >> 5, c = i & 31;
        sw[0][o][c] = wq[i] * SCALE;
        sw[1][o][c] = wk[i];
        sw[2][o][c] = wv[i];
    }
    if (t < 32) { sb[0][t] = bq[t] * SCALE; sb[1][t] = bk[t]; sb[2][t] = bv[t]; }
    __syncthreads();

    float xv[32];
    const float* xp = x + ((long)b * 32 * H_ + h) * 64 + tx;
    #pragma unroll
    for (int c = 0; c < 32; c++) xv[c] = xp[(long)c * H_ * 64];

    #pragma unroll
    for (int p = 0; p < 3; p++) {
        __half* dh = (p == 0) ? g_Q : (p == 1) ? g_K : g_V;
        #pragma unroll
        for (int o = 0; o < 32; o += 2) {
            float a0 = sb[p][o], a1 = sb[p][o + 1];
            #pragma unroll
            for (int c = 0; c < 32; c++) {
                a0 += sw[p][o][c] * xv[c];
                a1 += sw[p][o + 1][c] * xv[c];
            }
            sh[tx][ty * 16 + (o >> 1)] = pk(a0, a1);
        }
        __syncthreads();
        // writeout: per w, 64 uints (4 rows x 16 chpairs) contiguous in gmem
        uint32_t* gh = (uint32_t*)dh;
        const long cbase = (long)(b * 64) * 16384 + h0 * 16;
        for (int i = t; i < 4096; i += 256) {
            const int w = i >> 6, j = i & 63;
            gh[cbase + (long)w * 16384 + j] = sh[w][j];
        }
        __syncthreads();
    }
}

// ---------------------------------------------------------------------------
// Kernel 2: attention via mma.sync m16n8k16 fp16, single pass, cp.async
// double-buffered K/V. grid (bw=256, qt=8), block 256 (8 warps x 16 q rows).
// smem rows 80B pitch (64B data + 16B pad) -> conflict-free frag loads.
// ---------------------------------------------------------------------------
#define SQ   0
#define SKV0 10240
#define ATT_SMEM 51200   // Q 10K + 2 x (K 10K + V 10K)

__global__ void __launch_bounds__(256, 2) att3_kernel(
    const float* __restrict__ w_lin, const float* __restrict__ b_lin)
{
    extern __shared__ char sm[];
    const uint32_t sbase = smem_u32(sm);

    const int t = threadIdx.x;
    const int lane = t & 31, warp = t >> 5;
    const int bw = blockIdx.x, qt = blockIdx.y;

    const int qrow = lane >> 2;         // 0..7
    const int lc4 = (lane & 3) * 4;     // byte offset of pair
    const int wr = warp * 16;

    const size_t qbase = ((size_t)bw * H_ + (size_t)qt * 128) * 32;
    const size_t kvb = (size_t)bw * H_ * 32;

    // ---- group 0: Q tile + K/V tile 0 (buf 0) ----
    {
        const char* qg = (const char*)(g_Q + qbase);
        const char* kg = (const char*)(g_K + kvb);
        const char* vg = (const char*)(g_V + kvb);
        for (int i = t; i < 512; i += 256) {
            const uint32_t o = (i >> 2) * 80 + (i & 3) * 16;
            CP16(sbase + SQ + o, qg + i * 16);
            CP16(sbase + SKV0 + o, kg + i * 16);
            CP16(sbase + SKV0 + 10240 + o, vg + i * 16);
        }
        CP_COMMIT();
    }

    float sacc[16][4];
    float oacc[4][4];
    #pragma unroll
    for (int n = 0; n < 4; n++)
        #pragma unroll
        for (int e = 0; e < 4; e++) oacc[n][e] = 0.f;
    float rs0 = 0.f, rs1 = 0.f;

    for (int kt = 0; kt < 8; kt++) {
        if (kt < 7) {   // prefetch next tile into other buffer
            const char* kg = (const char*)(g_K + kvb + (size_t)(kt + 1) * 4096);
            const char* vg = (const char*)(g_V + kvb + (size_t)(kt + 1) * 4096);
            const uint32_t kb2 = sbase + SKV0 + ((kt + 1) & 1) * 20480;
            for (int i = t; i < 512; i += 256) {
                const uint32_t o = (i >> 2) * 80 + (i & 3) * 16;
                CP16(kb2 + o, kg + i * 16);
                CP16(kb2 + 10240 + o, vg + i * 16);
            }
            CP_COMMIT();
            CP_WAIT(1);
        } else {
            CP_WAIT(0);
        }
        __syncthreads();   // tile kt visible to all; prev buffer free for reuse

        const uint32_t kb = sbase + SKV0 + (kt & 1) * 20480;
        const uint32_t vb = kb + 10240;

        // ---- S = Q K^T (single pass) ----
        #pragma unroll
        for (int nt = 0; nt < 16; nt++) {
            sacc[nt][0] = 0.f; sacc[nt][1] = 0.f; sacc[nt][2] = 0.f; sacc[nt][3] = 0.f;
        }
        #pragma unroll
        for (int ks = 0; ks < 2; ks++) {
            const uint32_t aq = sbase + SQ + (wr + qrow) * 80 + lc4 + ks * 32;
            const uint32_t q0 = lds32(aq),      q1 = lds32(aq + 640);
            const uint32_t q2 = lds32(aq + 16), q3 = lds32(aq + 656);
            #pragma unroll
            for (int nt = 0; nt < 16; nt++) {
                const uint32_t bk = kb + (nt * 8 + qrow) * 80 + lc4 + ks * 32;
                MMA16816(sacc[nt], q0, q1, q2, q3, lds32(bk), lds32(bk + 16));
            }
        }

        // ---- P = exp(S) + row sums ----
        #pragma unroll
        for (int nt = 0; nt < 16; nt++) {
            const float e0 = __expf(sacc[nt][0]);
            const float e1 = __expf(sacc[nt][1]);
            const float e2 = __expf(sacc[nt][2]);
            const float e3 = __expf(sacc[nt][3]);
            rs0 += e0 + e1;
            rs1 += e2 + e3;
            sacc[nt][0] = e0; sacc[nt][1] = e1; sacc[nt][2] = e2; sacc[nt][3] = e3;
        }

        // ---- O += P V (single pass); A-frags from S accumulators ----
        #pragma unroll
        for (int ks = 0; ks < 8; ks++) {
            const float* p0 = sacc[2 * ks];
            const float* p1 = sacc[2 * ks + 1];
            const uint32_t a0 = pk(p0[0], p0[1]), a1 = pk(p0[2], p0[3]);
            const uint32_t a2 = pk(p1[0], p1[1]), a3 = pk(p1[2], p1[3]);
            const uint32_t va = vb + (ks * 16 + (lane & 15)) * 80;
            #pragma unroll
            for (int nt = 0; nt < 4; nt++) {
                uint32_t v0, v1;
                LDMX2T(v0, v1, va + nt * 16);
                MMA16816(oacc[nt], a0, a1, a2, a3, v0, v1);
            }
        }
        __syncthreads();   // all warps done with buffer kt before it's refilled
    }

    // ---- finalize: row sums across quad, scale+bias, store ----
    rs0 += __shfl_xor_sync(0xffffffffu, rs0, 1);
    rs0 += __shfl_xor_sync(0xffffffffu, rs0, 2);
    rs1 += __shfl_xor_sync(0xffffffffu, rs1, 1);
    rs1 += __shfl_xor_sync(0xffffffffu, rs1, 2);

    float ws = 0.f;
    #pragma unroll
    for (int k = 0; k < 8; k++) ws += w_lin[k];
    const float bb = b_lin[0];
    const float f0 = ws / rs0, f1 = ws / rs1;

    const int row = qt * 128 + wr + qrow;
    float* ob = g_O + ((size_t)bw * H_ + row) * 32 + (lane & 3) * 2;
    #pragma unroll
    for (int nt = 0; nt < 4; nt++) {
        float2 v0 = make_float2(oacc[nt][0] * f0 + bb, oacc[nt][1] * f0 + bb);
        float2 v1 = make_float2(oacc[nt][2] * f1 + bb, oacc[nt][3] * f1 + bb);
        *(float2*)(ob + nt * 8) = v0;
        *(float2*)(ob + 8 * 32 + nt * 8) = v1;
    }
}

// ---------------------------------------------------------------------------
// Kernel 3: epilogue transpose  g_O [bw][h][c] -> out [b][c][h][w]
// ---------------------------------------------------------------------------
__global__ void __launch_bounds__(256) transpose_kernel(float* __restrict__ out)
{
    __shared__ float tile[32][33];
    const int b = blockIdx.z, h = blockIdx.y, w0 = blockIdx.x * 32;

    for (int wi = threadIdx.y; wi < 32; wi += 8)
        tile[wi][threadIdx.x] = g_O[(((long)(b * 64 + w0 + wi)) * H_ + h) * 32 + threadIdx.x];
    __syncthreads();
    for (int c = threadIdx.y; c < 32; c += 8)
        out[(((long)(b * 32 + c)) * H_ + h) * 64 + w0 + threadIdx.x] = tile[threadIdx.x][c];
}

// ---------------------------------------------------------------------------
extern "C" void kernel_launch(void* const* d_in, const int* in_sizes, int n_in,
                              void* d_out, int out_size)
{
    const float* x  = (const float*)d_in[0];
    const float* wq = (const float*)d_in[1];
    const float* bq = (const float*)d_in[2];
    const float* wk = (const float*)d_in[3];
    const float* bk = (const float*)d_in[4];
    const float* wv = (const float*)d_in[5];
    const float* bv = (const float*)d_in[6];
    const float* wl = (const float*)d_in[7];
    const float* bl = (const float*)d_in[8];
    float* out = (float*)d_out;

    cudaFuncSetAttribute(att3_kernel, cudaFuncAttributeMaxDynamicSharedMemorySize, ATT_SMEM);

    proj_kernel<<<dim3(256, 4), dim3(64, 4)>>>(x, wq, bq, wk, bk, wv, bv);
    att3_kernel<<<dim3(256, 8), 256, ATT_SMEM>>>(wl, bl);
    transpose_kernel<<<dim3(2, 1024, 4), dim3(32, 8)>>>(out);
}

// round 8
// speedup vs baseline: 6.0296x; 1.0453x over previous
#include <cuda_runtime.h>
#include <cuda_fp16.h>
#include <cstdint>

#define B_ 4
#define C_ 32
#define H_ 1024
#define W_ 64
#define BW_ 256
// SCALE * log2(e): exp(s) computed as ex2(s') with scale folded into Q
#define PSCALE 0.12753139766698305f

// Scratch (__device__ globals; allocations forbidden). fp16 (calibrated R4-R6).
__device__ __half g_Q[BW_ * H_ * C_];   // [bw][h][c], pre-scaled by PSCALE
__device__ __half g_K[BW_ * H_ * C_];
__device__ __half g_V[BW_ * H_ * C_];
__device__ float  g_O[BW_ * H_ * C_];   // [bw][h][c] fp32

// ---------------------------------------------------------------------------
// helpers
// ---------------------------------------------------------------------------
__device__ __forceinline__ uint32_t smem_u32(const void* p) {
    uint32_t a;
    asm("{ .reg .u64 t; cvta.to.shared.u64 t, %1; cvt.u32.u64 %0, t; }" : "=r"(a) : "l"(p));
    return a;
}
__device__ __forceinline__ uint32_t lds32(uint32_t a) {
    uint32_t v;
    asm volatile("ld.shared.b32 %0, [%1];" : "=r"(v) : "r"(a));
    return v;
}
// pack two fp32 -> f16x2, e0 low half, e1 high half
__device__ __forceinline__ uint32_t pk(float e0, float e1) {
    uint32_t r;
    asm("cvt.rn.f16x2.f32 %0, %1, %2;" : "=r"(r) : "f"(e1), "f"(e0));
    return r;
}
__device__ __forceinline__ float ex2(float x) {
    float r;
    asm("ex2.approx.f32 %0, %1;" : "=f"(r) : "f"(x));
    return r;
}

#define MMA16816(d, a0, a1, a2, a3, b0, b1)                                    \
    asm volatile("mma.sync.aligned.m16n8k16.row.col.f32.f16.f16.f32 "          \
        "{%0,%1,%2,%3}, {%4,%5,%6,%7}, {%8,%9}, {%0,%1,%2,%3};"                \
        : "+f"((d)[0]), "+f"((d)[1]), "+f"((d)[2]), "+f"((d)[3])               \
        : "r"(a0), "r"(a1), "r"(a2), "r"(a3), "r"(b0), "r"(b1))

#define LDMX2T(r0, r1, addr)                                                   \
    asm volatile("ldmatrix.sync.aligned.m8n8.x2.trans.shared.b16 {%0,%1}, [%2];" \
        : "=r"(r0), "=r"(r1) : "r"(addr))

#define CP16(dst, src)                                                         \
    asm volatile("cp.async.cg.shared.global [%0], [%1], 16;" :: "r"(dst), "l"(src))
#define CP_COMMIT() asm volatile("cp.async.commit_group;")
#define CP_WAIT(n)  asm volatile("cp.async.wait_group %0;" :: "n"(n))

// ---------------------------------------------------------------------------
// Kernel 1: tensor-core QKV projection.
// Per CTA: A = x rows [(2h x 64w) = 128 rows x 32c] (fp16 hi/lo, 2-pass),
// B = stacked [Wq*PSCALE; Wk; Wv] [96 x 32] fp16 (rounded once).
// grid (512 htiles, 4 b), 256 threads (8 warps x 16 rows).
// ---------------------------------------------------------------------------
#define PXH 0
#define PXL 10240
#define PW  20480
#define PBI 28160
__global__ void __launch_bounds__(256) proj_tc(
    const float* __restrict__ x,
    const float* __restrict__ wq, const float* __restrict__ bq,
    const float* __restrict__ wk, const float* __restrict__ bk,
    const float* __restrict__ wv, const float* __restrict__ bv)
{
    __shared__ __align__(16) char sm[28544];
    const uint32_t sbase = smem_u32(sm);

    const int t = threadIdx.x;
    const int lane = t & 31, warp = t >> 5;
    const int b = blockIdx.y;
    const int h0 = blockIdx.x * 2;

    // ---- W -> smem [o][c] fp16, rows 80B pitch; o: 0-31 q, 32-63 k, 64-95 v
    for (int i = t; i < 3072; i += 256) {
        const int o = i >> 5, c = i & 31;
        float v = (o < 32) ? wq[o * 32 + c] * PSCALE
                : (o < 64) ? wk[(o - 32) * 32 + c]
                           : wv[(o - 64) * 32 + c];
        *(__half*)(sm + PW + o * 80 + c * 2) = __float2half_rn(v);
    }
    if (t < 96) {
        float v = (t < 32) ? bq[t] * PSCALE : (t < 64) ? bk[t - 32] : bv[t - 64];
        *(float*)(sm + PBI + t * 4) = v;
    }

    // ---- x -> smem hi/lo [r][c], r = h_local*64 + w  (rows 80B pitch)
    const float4* xp4 = (const float4*)x;
    for (int i = t; i < 1024; i += 256) {
        const int c = i >> 5, j = i & 31;
        float4 v = xp4[(size_t)(b * 32 + c) * 16384 + h0 * 16 + j];
        #pragma unroll
        for (int e = 0; e < 4; e++) {
            const float f = (e == 0) ? v.x : (e == 1) ? v.y : (e == 2) ? v.z : v.w;
            const __half hh = __float2half_rn(f);
            const int r = j * 4 + e;
            *(__half*)(sm + PXH + r * 80 + c * 2) = hh;
            *(__half*)(sm + PXL + r * 80 + c * 2) = __float2half_rn(f - __half2float(hh));
        }
    }
    __syncthreads();

    // ---- GEMM: 12 n-tiles x 2 ksteps x 2 passes = 48 MMA/warp
    const int qrow = lane >> 2;
    const int lc4 = (lane & 3) * 4;
    const int wr = warp * 16;

    float acc[12][4];
    #pragma unroll
    for (int nt = 0; nt < 12; nt++) {
        acc[nt][0] = 0.f; acc[nt][1] = 0.f; acc[nt][2] = 0.f; acc[nt][3] = 0.f;
    }
    #pragma unroll
    for (int ks = 0; ks < 2; ks++) {
        const uint32_t aq = sbase + PXH + (wr + qrow) * 80 + lc4 + ks * 32;
        const uint32_t h0r = lds32(aq),         h1r = lds32(aq + 640);
        const uint32_t h2r = lds32(aq + 16),    h3r = lds32(aq + 656);
        const uint32_t l0r = lds32(aq + 10240), l1r = lds32(aq + 10880);
        const uint32_t l2r = lds32(aq + 10256), l3r = lds32(aq + 10896);
        #pragma unroll
        for (int nt = 0; nt < 12; nt++) {
            const uint32_t bk2 = sbase + PW + (nt * 8 + qrow) * 80 + lc4 + ks * 32;
            const uint32_t b0 = lds32(bk2), b1 = lds32(bk2 + 16);
            MMA16816(acc[nt], h0r, h1r, h2r, h3r, b0, b1);
            MMA16816(acc[nt], l0r, l1r, l2r, l3r, b0, b1);
        }
    }

    // ---- epilogue: +bias, round fp16, store pairs
    const int r0 = wr + qrow, r1 = r0 + 8;
    const size_t d0base = ((size_t)(b * 64 + (r0 & 63)) * 1024 + h0 + (r0 >> 6)) * 32;
    const size_t d1base = ((size_t)(b * 64 + (r1 & 63)) * 1024 + h0 + (r1 >> 6)) * 32;
    #pragma unroll
    for (int nt = 0; nt < 12; nt++) {
        const int tensor = nt >> 2;
        const int c0 = (nt & 3) * 8 + (lane & 3) * 2;
        const float2 bi = *(const float2*)(sm + PBI + (tensor * 32 + c0) * 4);
        __half* g = (tensor == 0) ? g_Q : (tensor == 1) ? g_K : g_V;
        *(uint32_t*)(g + d0base + c0) = pk(acc[nt][0] + bi.x, acc[nt][1] + bi.y);
        *(uint32_t*)(g + d1base + c0) = pk(acc[nt][2] + bi.x, acc[nt][3] + bi.y);
    }
}

// ---------------------------------------------------------------------------
// Kernel 2: attention, mma.sync fp16, cp.async double-buffered K/V,
// rowsum via ones-column in V's pad bytes (5th n-tile).
// grid (bw=256, qt=8), block 256. Rows 80B pitch.
// ---------------------------------------------------------------------------
#define SQ   0
#define SKV0 10240
#define ATT_SMEM 51200   // Q 10K + 2 x (K 10K + V 10K)

__global__ void __launch_bounds__(256, 2) att3_kernel(
    const float* __restrict__ w_lin, const float* __restrict__ b_lin)
{
    extern __shared__ char sm[];
    const uint32_t sbase = smem_u32(sm);

    const int t = threadIdx.x;
    const int lane = t & 31, warp = t >> 5;
    const int bw = blockIdx.x, qt = blockIdx.y;

    const int qrow = lane >> 2;
    const int lc4 = (lane & 3) * 4;
    const int wr = warp * 16;

    const size_t qbase = ((size_t)bw * H_ + (size_t)qt * 128) * 32;
    const size_t kvb = (size_t)bw * H_ * 32;

    // ---- ones-column init: V pad bytes (64..79 of each 80B row), both buffers.
    // ch32 = 1.0h, ch33..39 = 0. cp.async never touches these bytes.
    {
        const int buf = t >> 7, row = t & 127;
        *(uint4*)(sm + SKV0 + buf * 20480 + 10240 + row * 80 + 64) =
            make_uint4(0x00003C00u, 0u, 0u, 0u);
    }

    // ---- group 0: Q tile + K/V tile 0 (buf 0) ----
    {
        const char* qg = (const char*)(g_Q + qbase);
        const char* kg = (const char*)(g_K + kvb);
        const char* vg = (const char*)(g_V + kvb);
        for (int i = t; i < 512; i += 256) {
            const uint32_t o = (i >> 2) * 80 + (i & 3) * 16;
            CP16(sbase + SQ + o, qg + i * 16);
            CP16(sbase + SKV0 + o, kg + i * 16);
            CP16(sbase + SKV0 + 10240 + o, vg + i * 16);
        }
        CP_COMMIT();
    }

    float sacc[16][4];
    float oacc[5][4];
    #pragma unroll
    for (int n = 0; n < 5; n++)
        #pragma unroll
        for (int e = 0; e < 4; e++) oacc[n][e] = 0.f;

    for (int kt = 0; kt < 8; kt++) {
        if (kt < 7) {   // prefetch next tile into other buffer
            const char* kg = (const char*)(g_K + kvb + (size_t)(kt + 1) * 4096);
            const char* vg = (const char*)(g_V + kvb + (size_t)(kt + 1) * 4096);
            const uint32_t kb2 = sbase + SKV0 + ((kt + 1) & 1) * 20480;
            for (int i = t; i < 512; i += 256) {
                const uint32_t o = (i >> 2) * 80 + (i & 3) * 16;
                CP16(kb2 + o, kg + i * 16);
                CP16(kb2 + 10240 + o, vg + i * 16);
            }
            CP_COMMIT();
            CP_WAIT(1);
        } else {
            CP_WAIT(0);
        }
        __syncthreads();

        const uint32_t kb = sbase + SKV0 + (kt & 1) * 20480;
        const uint32_t vb = kb + 10240;

        // ---- S' = Q K^T (scores pre-scaled by log2e) ----
        #pragma unroll
        for (int nt = 0; nt < 16; nt++) {
            sacc[nt][0] = 0.f; sacc[nt][1] = 0.f; sacc[nt][2] = 0.f; sacc[nt][3] = 0.f;
        }
        #pragma unroll
        for (int ks = 0; ks < 2; ks++) {
            const uint32_t aq = sbase + SQ + (wr + qrow) * 80 + lc4 + ks * 32;
            const uint32_t q0 = lds32(aq),      q1 = lds32(aq + 640);
            const uint32_t q2 = lds32(aq + 16), q3 = lds32(aq + 656);
            #pragma unroll
            for (int nt = 0; nt < 16; nt++) {
                const uint32_t bk = kb + (nt * 8 + qrow) * 80 + lc4 + ks * 32;
                MMA16816(sacc[nt], q0, q1, q2, q3, lds32(bk), lds32(bk + 16));
            }
        }

        // ---- P = 2^(S') — bare MUFU, no row-sum adds ----
        #pragma unroll
        for (int nt = 0; nt < 16; nt++) {
            sacc[nt][0] = ex2(sacc[nt][0]);
            sacc[nt][1] = ex2(sacc[nt][1]);
            sacc[nt][2] = ex2(sacc[nt][2]);
            sacc[nt][3] = ex2(sacc[nt][3]);
        }

        // ---- O += P [V | 1]  (5 n-tiles; nt=4 = ones column -> rowsum) ----
        #pragma unroll
        for (int ks = 0; ks < 8; ks++) {
            const float* p0 = sacc[2 * ks];
            const float* p1 = sacc[2 * ks + 1];
            const uint32_t a0 = pk(p0[0], p0[1]), a1 = pk(p0[2], p0[3]);
            const uint32_t a2 = pk(p1[0], p1[1]), a3 = pk(p1[2], p1[3]);
            const uint32_t va = vb + (ks * 16 + (lane & 15)) * 80;
            #pragma unroll
            for (int nt = 0; nt < 5; nt++) {
                uint32_t v0, v1;
                LDMX2T(v0, v1, va + nt * 16);
                MMA16816(oacc[nt], a0, a1, a2, a3, v0, v1);
            }
        }
        __syncthreads();
    }

    // ---- finalize: rowsums live in oacc[4] col ch32 (lane&3==0) ----
    const float rs0 = __shfl_sync(0xffffffffu, oacc[4][0], lane & 28);
    const float rs1 = __shfl_sync(0xffffffffu, oacc[4][2], lane & 28);

    float ws = 0.f;
    #pragma unroll
    for (int k = 0; k < 8; k++) ws += w_lin[k];
    const float bb = b_lin[0];
    const float f0 = ws / rs0, f1 = ws / rs1;

    const int row = qt * 128 + wr + qrow;
    float* ob = g_O + ((size_t)bw * H_ + row) * 32 + (lane & 3) * 2;
    #pragma unroll
    for (int nt = 0; nt < 4; nt++) {
        float2 v0 = make_float2(oacc[nt][0] * f0 + bb, oacc[nt][1] * f0 + bb);
        float2 v1 = make_float2(oacc[nt][2] * f1 + bb, oacc[nt][3] * f1 + bb);
        *(float2*)(ob + nt * 8) = v0;
        *(float2*)(ob + 8 * 32 + nt * 8) = v1;
    }
}

// ---------------------------------------------------------------------------
// Kernel 3: epilogue transpose  g_O [bw][h][c] -> out [b][c][h][w]
// ---------------------------------------------------------------------------
__global__ void __launch_bounds__(256) transpose_kernel(float* __restrict__ out)
{
    __shared__ float tile[32][33];
    const int b = blockIdx.z, h = blockIdx.y, w0 = blockIdx.x * 32;

    for (int wi = threadIdx.y; wi < 32; wi += 8)
        tile[wi][threadIdx.x] = g_O[(((long)(b * 64 + w0 + wi)) * H_ + h) * 32 + threadIdx.x];
    __syncthreads();
    for (int c = threadIdx.y; c < 32; c += 8)
        out[(((long)(b * 32 + c)) * H_ + h) * 64 + w0 + threadIdx.x] = tile[threadIdx.x][c];
}

// ---------------------------------------------------------------------------
extern "C" void kernel_launch(void* const* d_in, const int* in_sizes, int n_in,
                              void* d_out, int out_size)
{
    const float* x  = (const float*)d_in[0];
    const float* wq = (const float*)d_in[1];
    const float* bq = (const float*)d_in[2];
    const float* wk = (const float*)d_in[3];
    const float* bk = (const float*)d_in[4];
    const float* wv = (const float*)d_in[5];
    const float* bv = (const float*)d_in[6];
    const float* wl = (const float*)d_in[7];
    const float* bl = (const float*)d_in[8];
    float* out = (float*)d_out;

    cudaFuncSetAttribute(att3_kernel, cudaFuncAttributeMaxDynamicSharedMemorySize, ATT_SMEM);

    proj_tc<<<dim3(512, 4), 256>>>(x, wq, bq, wk, bk, wv, bv);
    att3_kernel<<<dim3(256, 8), 256, ATT_SMEM>>>(wl, bl);
    transpose_kernel<<<dim3(2, 1024, 4), dim3(32, 8)>>>(out);
}